// round 1
// baseline (speedup 1.0000x reference)
#include <cuda_runtime.h>

#define Bdim 4
#define Tdim 256
#define Sdim 256
#define Ddim 512

// Scratch (allocation-free rule: __device__ globals)
__device__ float g_wq[Bdim * Tdim * Ddim];   // 2 MB
__device__ float g_uh[Bdim * Sdim * Ddim];   // 2 MB
__device__ float g_sc[Bdim * Tdim * Sdim];   // 1 MB (scores, then attn in-place)
__device__ float g_mix[Bdim * Tdim * Ddim];  // 2 MB

__device__ __forceinline__ float tanh_fast(float x) {
    float y;
    asm("tanh.approx.f32 %0, %1;" : "=f"(y) : "f"(x));
    return y;
}

// ---------------------------------------------------------------------------
// Generic 64x64x16 SGEMM: C = A @ W (+ bias), optional batch strides.
// A: M x K row-major, W: K x N row-major, C: M x N. 256 threads, 4x4/thread.
// All dims must be multiples of the tile sizes (true for this problem).
// ---------------------------------------------------------------------------
__global__ __launch_bounds__(256) void sgemm_kernel(
    const float* __restrict__ A, const float* __restrict__ W,
    const float* __restrict__ bias, float* __restrict__ C,
    int M, int N, int K, long sA, long sW, long sC)
{
    __shared__ float As[16][64];  // [k][m]
    __shared__ float Ws[16][64];  // [k][n]

    A += (long)blockIdx.z * sA;
    W += (long)blockIdx.z * sW;
    C += (long)blockIdx.z * sC;

    const int tid = threadIdx.x;
    const int tx = tid & 15, ty = tid >> 4;
    const int row0 = blockIdx.y * 64;
    const int col0 = blockIdx.x * 64;

    const int la_m = tid >> 2;          // 0..63
    const int la_k = (tid & 3) << 2;    // 0,4,8,12
    const int lw_k = tid >> 4;          // 0..15
    const int lw_n = (tid & 15) << 2;   // 0..60

    float acc[4][4] = {};

    for (int k0 = 0; k0 < K; k0 += 16) {
        float4 a = *(const float4*)&A[(long)(row0 + la_m) * K + k0 + la_k];
        As[la_k + 0][la_m] = a.x;
        As[la_k + 1][la_m] = a.y;
        As[la_k + 2][la_m] = a.z;
        As[la_k + 3][la_m] = a.w;
        *(float4*)&Ws[lw_k][lw_n] =
            *(const float4*)&W[(long)(k0 + lw_k) * N + col0 + lw_n];
        __syncthreads();

#pragma unroll
        for (int kk = 0; kk < 16; kk++) {
            float4 av = *(const float4*)&As[kk][ty * 4];
            float4 wv = *(const float4*)&Ws[kk][tx * 4];
            float aa[4] = {av.x, av.y, av.z, av.w};
            float ww[4] = {wv.x, wv.y, wv.z, wv.w};
#pragma unroll
            for (int i = 0; i < 4; i++)
#pragma unroll
                for (int j = 0; j < 4; j++)
                    acc[i][j] += aa[i] * ww[j];
        }
        __syncthreads();
    }

    float b4[4] = {0.f, 0.f, 0.f, 0.f};
    if (bias) {
#pragma unroll
        for (int j = 0; j < 4; j++) b4[j] = bias[col0 + tx * 4 + j];
    }
#pragma unroll
    for (int i = 0; i < 4; i++) {
        int r = row0 + ty * 4 + i;
        float4 o;
        o.x = acc[i][0] + b4[0];
        o.y = acc[i][1] + b4[1];
        o.z = acc[i][2] + b4[2];
        o.w = acc[i][3] + b4[3];
        *(float4*)&C[(long)r * N + col0 + tx * 4] = o;
    }
}

// ---------------------------------------------------------------------------
// Final projection: out = [mix | output] @ Wout + bout.  K = 2*512 split.
// ---------------------------------------------------------------------------
__global__ __launch_bounds__(256) void sgemm_concat_kernel(
    const float* __restrict__ A1, const float* __restrict__ A2,
    const float* __restrict__ W, const float* __restrict__ bias,
    float* __restrict__ C, int N)
{
    __shared__ float As[16][64];
    __shared__ float Ws[16][64];

    const int tid = threadIdx.x;
    const int tx = tid & 15, ty = tid >> 4;
    const int row0 = blockIdx.y * 64;
    const int col0 = blockIdx.x * 64;

    const int la_m = tid >> 2;
    const int la_k = (tid & 3) << 2;
    const int lw_k = tid >> 4;
    const int lw_n = (tid & 15) << 2;

    float acc[4][4] = {};

    for (int k0 = 0; k0 < 2 * Ddim; k0 += 16) {
        int kg = k0 + la_k;
        const float* src = (kg < Ddim)
                               ? &A1[(long)(row0 + la_m) * Ddim + kg]
                               : &A2[(long)(row0 + la_m) * Ddim + kg - Ddim];
        float4 a = *(const float4*)src;
        As[la_k + 0][la_m] = a.x;
        As[la_k + 1][la_m] = a.y;
        As[la_k + 2][la_m] = a.z;
        As[la_k + 3][la_m] = a.w;
        *(float4*)&Ws[lw_k][lw_n] =
            *(const float4*)&W[(long)(k0 + lw_k) * N + col0 + lw_n];
        __syncthreads();

#pragma unroll
        for (int kk = 0; kk < 16; kk++) {
            float4 av = *(const float4*)&As[kk][ty * 4];
            float4 wv = *(const float4*)&Ws[kk][tx * 4];
            float aa[4] = {av.x, av.y, av.z, av.w};
            float ww[4] = {wv.x, wv.y, wv.z, wv.w};
#pragma unroll
            for (int i = 0; i < 4; i++)
#pragma unroll
                for (int j = 0; j < 4; j++)
                    acc[i][j] += aa[i] * ww[j];
        }
        __syncthreads();
    }

    float b4[4];
#pragma unroll
    for (int j = 0; j < 4; j++) b4[j] = bias[col0 + tx * 4 + j];
#pragma unroll
    for (int i = 0; i < 4; i++) {
        int r = row0 + ty * 4 + i;
        float4 o;
        o.x = acc[i][0] + b4[0];
        o.y = acc[i][1] + b4[1];
        o.z = acc[i][2] + b4[2];
        o.w = acc[i][3] + b4[3];
        *(float4*)&C[(long)r * N + col0 + tx * 4] = o;
    }
}

// ---------------------------------------------------------------------------
// score[b,t,s] = sum_d v[d] * tanh(wq[b,t,d] + uh[b,s,d])
// grid (S/32, T/32, B); 256 threads; 32x32 tile, 2x2 per thread; D chunk 32.
// MUFU(tanh)-bound by design.
// ---------------------------------------------------------------------------
__global__ __launch_bounds__(256) void score_kernel(
    const float* __restrict__ wq, const float* __restrict__ uh,
    const float* __restrict__ v, float* __restrict__ sc)
{
    __shared__ float Aq[32][33];  // [d][t]
    __shared__ float Au[32][33];  // [d][s]
    __shared__ float vs[32];

    const int b = blockIdx.z;
    const int t0 = blockIdx.y * 32;
    const int s0 = blockIdx.x * 32;
    const int tid = threadIdx.x;
    const int tx = tid & 15, ty = tid >> 4;

    const float* wqb = wq + ((long)b * Tdim + t0) * Ddim;
    const float* uhb = uh + ((long)b * Sdim + s0) * Ddim;

    const int lr = tid >> 3;         // 0..31  (row within tile)
    const int lc = (tid & 7) << 2;   // 0..28  (d offset, float4)

    float acc00 = 0.f, acc01 = 0.f, acc10 = 0.f, acc11 = 0.f;

    for (int d0 = 0; d0 < Ddim; d0 += 32) {
        float4 q = *(const float4*)&wqb[(long)lr * Ddim + d0 + lc];
        Aq[lc + 0][lr] = q.x;
        Aq[lc + 1][lr] = q.y;
        Aq[lc + 2][lr] = q.z;
        Aq[lc + 3][lr] = q.w;
        float4 u = *(const float4*)&uhb[(long)lr * Ddim + d0 + lc];
        Au[lc + 0][lr] = u.x;
        Au[lc + 1][lr] = u.y;
        Au[lc + 2][lr] = u.z;
        Au[lc + 3][lr] = u.w;
        if (tid < 32) vs[tid] = v[d0 + tid];
        __syncthreads();

#pragma unroll
        for (int dk = 0; dk < 32; dk++) {
            float vv = vs[dk];
            float a0 = Aq[dk][ty * 2 + 0];
            float a1 = Aq[dk][ty * 2 + 1];
            float u0 = Au[dk][tx * 2 + 0];
            float u1 = Au[dk][tx * 2 + 1];
            acc00 += vv * tanh_fast(a0 + u0);
            acc01 += vv * tanh_fast(a0 + u1);
            acc10 += vv * tanh_fast(a1 + u0);
            acc11 += vv * tanh_fast(a1 + u1);
        }
        __syncthreads();
    }

    float* scp = sc + ((long)b * Tdim + t0) * Sdim + s0;
    scp[(long)(ty * 2 + 0) * Sdim + tx * 2 + 0] = acc00;
    scp[(long)(ty * 2 + 0) * Sdim + tx * 2 + 1] = acc01;
    scp[(long)(ty * 2 + 1) * Sdim + tx * 2 + 0] = acc10;
    scp[(long)(ty * 2 + 1) * Sdim + tx * 2 + 1] = acc11;
}

// ---------------------------------------------------------------------------
// Masked softmax per (b,t) row, exactly matching reference semantics:
// max over ALL s, then zero masked entries, renormalize.
// One block (256 threads) per row; attn written in-place + optionally to d_out.
// ---------------------------------------------------------------------------
__global__ __launch_bounds__(256) void softmax_kernel(
    float* __restrict__ sc, const int* __restrict__ mask,
    float* __restrict__ attn_out)
{
    __shared__ float sm[8];
    __shared__ float ss[8];

    const int row = blockIdx.x;          // b*T + t
    const int b = row / Tdim;
    const int s = threadIdx.x;
    const long idx = (long)row * Sdim + s;

    float x = sc[idx];

    float m = x;
#pragma unroll
    for (int o = 16; o > 0; o >>= 1)
        m = fmaxf(m, __shfl_xor_sync(0xffffffffu, m, o));
    const int warp = s >> 5, lane = s & 31;
    if (lane == 0) sm[warp] = m;
    __syncthreads();
    float mx = sm[0];
#pragma unroll
    for (int w = 1; w < 8; w++) mx = fmaxf(mx, sm[w]);

    const float keep = 1.0f - (float)mask[b * Sdim + s];
    const float e = __expf(x - mx) * keep;

    float t = e;
#pragma unroll
    for (int o = 16; o > 0; o >>= 1)
        t += __shfl_xor_sync(0xffffffffu, t, o);
    if (lane == 0) ss[warp] = t;
    __syncthreads();
    float sum = ss[0];
#pragma unroll
    for (int w = 1; w < 8; w++) sum += ss[w];

    const float a = e / sum;
    sc[idx] = a;
    if (attn_out) attn_out[idx] = a;
}

// ---------------------------------------------------------------------------
extern "C" void kernel_launch(void* const* d_in, const int* in_sizes, int n_in,
                              void* d_out, int out_size)
{
    const float* out_in = (const float*)d_in[0];  // (B,T,D)
    const float* ctx    = (const float*)d_in[1];  // (B,S,D)
    const int*   mask   = (const int*)d_in[2];    // (B,S)
    const float* Wq     = (const float*)d_in[3];  // (D,D)
    const float* bq     = (const float*)d_in[4];  // (D,)
    const float* Wc     = (const float*)d_in[5];  // (D,D)
    const float* v      = (const float*)d_in[6];  // (D,)
    const float* Wout   = (const float*)d_in[7];  // (2D,D)
    const float* bout   = (const float*)d_in[8];  // (D,)

    float *p_wq, *p_uh, *p_sc, *p_mix;
    cudaGetSymbolAddress((void**)&p_wq, g_wq);
    cudaGetSymbolAddress((void**)&p_uh, g_uh);
    cudaGetSymbolAddress((void**)&p_sc, g_sc);
    cudaGetSymbolAddress((void**)&p_mix, g_mix);

    const long BTD = (long)Bdim * Tdim * Ddim;  // 524288
    const long BTS = (long)Bdim * Tdim * Sdim;  // 262144
    float* out_f = (float*)d_out;
    float* attn_out = ((long)out_size >= BTD + BTS) ? (out_f + BTD) : nullptr;

    dim3 blk(256);

    // 1) wq = output @ Wq + bq   (1024 x 512 x 512)
    sgemm_kernel<<<dim3(Ddim / 64, (Bdim * Tdim) / 64, 1), blk>>>(
        out_in, Wq, bq, p_wq, Bdim * Tdim, Ddim, Ddim, 0, 0, 0);

    // 2) uh = context @ Wc       (1024 x 512 x 512)
    sgemm_kernel<<<dim3(Ddim / 64, (Bdim * Sdim) / 64, 1), blk>>>(
        ctx, Wc, nullptr, p_uh, Bdim * Sdim, Ddim, Ddim, 0, 0, 0);

    // 3) score
    score_kernel<<<dim3(Sdim / 32, Tdim / 32, Bdim), blk>>>(p_wq, p_uh, v, p_sc);

    // 4) masked softmax (attn in-place in g_sc, also to d_out attn region)
    softmax_kernel<<<Bdim * Tdim, Sdim>>>(p_sc, mask, attn_out);

    // 5) mix = attn @ context    (batched 256 x 512 x 256)
    sgemm_kernel<<<dim3(Ddim / 64, Tdim / 64, Bdim), blk>>>(
        p_sc, ctx, nullptr, p_mix, Tdim, Ddim, Sdim,
        (long)Tdim * Sdim, (long)Sdim * Ddim, (long)Tdim * Ddim);

    // 6) out = [mix | output] @ Wout + bout  (1024 x 512 x 1024)
    sgemm_concat_kernel<<<dim3(Ddim / 64, (Bdim * Tdim) / 64, 1), blk>>>(
        p_mix, out_in, Wout, bout, out_f, Ddim);
}

// round 3
// speedup vs baseline: 1.0766x; 1.0766x over previous
#include <cuda_runtime.h>
#include <cstdint>

#define Bdim 4
#define Tdim 256
#define Sdim 256
#define Ddim 512

// Scratch (allocation-free rule: __device__ globals)
__device__ float g_wq[Bdim * Tdim * Ddim];   // 2 MB
__device__ float g_uh[Bdim * Sdim * Ddim];   // 2 MB
__device__ float g_sc[Bdim * Tdim * Sdim];   // 1 MB (scores, then attn in-place)
__device__ float g_mix[Bdim * Tdim * Ddim];  // 2 MB

__device__ __forceinline__ float tanh_fast(float x) {
    float y;
    asm("tanh.approx.f32 %0, %1;" : "=f"(y) : "f"(x));
    return y;
}

__device__ __forceinline__ uint32_t f2tf32(float x) {
    uint32_t y;
    asm("cvt.rna.tf32.f32 %0, %1;" : "=r"(y) : "f"(x));
    return y;
}

__device__ __forceinline__ void mma_tf32(float* d, const uint32_t* a,
                                         const uint32_t* b) {
    asm volatile(
        "mma.sync.aligned.m16n8k8.row.col.f32.tf32.tf32.f32 "
        "{%0,%1,%2,%3}, {%4,%5,%6,%7}, {%8,%9}, {%0,%1,%2,%3};"
        : "+f"(d[0]), "+f"(d[1]), "+f"(d[2]), "+f"(d[3])
        : "r"(a[0]), "r"(a[1]), "r"(a[2]), "r"(a[3]), "r"(b[0]), "r"(b[1]));
}

// ---------------------------------------------------------------------------
// tf32 mma.sync GEMM: C[M,N] = concat_k(A1,A2)[M,K] @ B[K,N] (+bias)
// Block tile 128(M) x 64(N), BK=16, 256 threads = 8 warps (4m x 2n),
// warp tile 32x32 (2 m-frags x 4 n-frags of m16n8k8). Double-buffered smem.
// A smem [k][m] pad 136 (8 mod 32 -> conflict-free frag LDS);
// B smem [k][n] pad 72.
// Batch via blockIdx.z with strides sA, sB, sC (A2 shares sA).
// ---------------------------------------------------------------------------
#define LDA_S 136
#define LDB_S 72

__global__ __launch_bounds__(256) void mma_gemm(
    const float* __restrict__ A1, const float* __restrict__ A2, int Ksplit,
    const float* __restrict__ Bmat, const float* __restrict__ bias,
    float* __restrict__ C, int M, int N, int K,
    long sA, long sB, long sC)
{
    __shared__ uint32_t As[2][16 * LDA_S];
    __shared__ uint32_t Bs[2][16 * LDB_S];

    const int tid = threadIdx.x;
    const int wid = tid >> 5;
    const int lane = tid & 31;
    const int g = lane >> 2;    // 0..7
    const int tig = lane & 3;   // 0..3
    const int warp_m = wid >> 1;  // 0..3
    const int warp_n = wid & 1;   // 0..1
    const int z = blockIdx.z;

    const float* A1p = A1 + (long)z * sA;
    const float* A2p = A2 + (long)z * sA;
    const float* Bp  = Bmat + (long)z * sB;
    float* Cp        = C + (long)z * sC;

    const int m0 = blockIdx.y * 128;
    const int n0 = blockIdx.x * 64;
    const int ldA1 = Ksplit;
    const int ldA2 = K - Ksplit;

    // gmem->smem mapping
    const int m_ld = tid & 127;          // A row within tile
    const int kq_ld = (tid >> 7) << 3;   // 0 or 8
    const int kb_ld = tid >> 4;          // 0..15 (B k-row)
    const int nb_ld = (tid & 15) << 2;   // 0..60

    float acc[2][4][4];
#pragma unroll
    for (int i = 0; i < 2; i++)
#pragma unroll
        for (int j = 0; j < 4; j++)
#pragma unroll
            for (int q = 0; q < 4; q++) acc[i][j][q] = 0.f;

    const int NT = K >> 4;

    float4 va0, va1, vb;
    // prologue fetch tile 0
    {
        const float* Asrc;
        int lda;
        if (0 < Ksplit) { Asrc = A1p; lda = ldA1; }
        else            { Asrc = A2p; lda = ldA2; }
        const float* ap = Asrc + (long)(m0 + m_ld) * lda + kq_ld;
        va0 = *(const float4*)ap;
        va1 = *(const float4*)(ap + 4);
        vb  = *(const float4*)(Bp + (long)kb_ld * N + n0 + nb_ld);
    }
    // store tile 0
    {
        uint32_t* as = As[0];
        as[(kq_ld + 0) * LDA_S + m_ld] = f2tf32(va0.x);
        as[(kq_ld + 1) * LDA_S + m_ld] = f2tf32(va0.y);
        as[(kq_ld + 2) * LDA_S + m_ld] = f2tf32(va0.z);
        as[(kq_ld + 3) * LDA_S + m_ld] = f2tf32(va0.w);
        as[(kq_ld + 4) * LDA_S + m_ld] = f2tf32(va1.x);
        as[(kq_ld + 5) * LDA_S + m_ld] = f2tf32(va1.y);
        as[(kq_ld + 6) * LDA_S + m_ld] = f2tf32(va1.z);
        as[(kq_ld + 7) * LDA_S + m_ld] = f2tf32(va1.w);
        uint4 w = make_uint4(f2tf32(vb.x), f2tf32(vb.y), f2tf32(vb.z), f2tf32(vb.w));
        *(uint4*)&Bs[0][kb_ld * LDB_S + nb_ld] = w;
    }
    __syncthreads();

    for (int t = 0; t < NT; t++) {
        const int buf = t & 1;

        // fetch next tile into regs (overlap with compute)
        if (t + 1 < NT) {
            const int kg = (t + 1) << 4;
            const float* Asrc;
            int lda, koff;
            if (kg < Ksplit) { Asrc = A1p; lda = ldA1; koff = kg; }
            else             { Asrc = A2p; lda = ldA2; koff = kg - Ksplit; }
            const float* ap = Asrc + (long)(m0 + m_ld) * lda + koff + kq_ld;
            va0 = *(const float4*)ap;
            va1 = *(const float4*)(ap + 4);
            vb  = *(const float4*)(Bp + (long)(kg + kb_ld) * N + n0 + nb_ld);
        }

        // compute on buf
        {
            const uint32_t* as = As[buf];
            const uint32_t* bs = Bs[buf];
            const int mb = warp_m * 32;
            const int nb = warp_n * 32;
#pragma unroll
            for (int ks = 0; ks < 2; ks++) {
                const int k0 = ks << 3;
                uint32_t a[2][4], b[4][2];
#pragma unroll
                for (int im = 0; im < 2; im++) {
                    const int mr = mb + im * 16 + g;
                    a[im][0] = as[(k0 + tig) * LDA_S + mr];
                    a[im][1] = as[(k0 + tig) * LDA_S + mr + 8];
                    a[im][2] = as[(k0 + tig + 4) * LDA_S + mr];
                    a[im][3] = as[(k0 + tig + 4) * LDA_S + mr + 8];
                }
#pragma unroll
                for (int in = 0; in < 4; in++) {
                    const int nc = nb + in * 8 + g;
                    b[in][0] = bs[(k0 + tig) * LDB_S + nc];
                    b[in][1] = bs[(k0 + tig + 4) * LDB_S + nc];
                }
#pragma unroll
                for (int im = 0; im < 2; im++)
#pragma unroll
                    for (int in = 0; in < 4; in++)
                        mma_tf32(acc[im][in], a[im], b[in]);
            }
        }

        // store next tile
        if (t + 1 < NT) {
            const int nbuf = buf ^ 1;
            uint32_t* as = As[nbuf];
            as[(kq_ld + 0) * LDA_S + m_ld] = f2tf32(va0.x);
            as[(kq_ld + 1) * LDA_S + m_ld] = f2tf32(va0.y);
            as[(kq_ld + 2) * LDA_S + m_ld] = f2tf32(va0.z);
            as[(kq_ld + 3) * LDA_S + m_ld] = f2tf32(va0.w);
            as[(kq_ld + 4) * LDA_S + m_ld] = f2tf32(va1.x);
            as[(kq_ld + 5) * LDA_S + m_ld] = f2tf32(va1.y);
            as[(kq_ld + 6) * LDA_S + m_ld] = f2tf32(va1.z);
            as[(kq_ld + 7) * LDA_S + m_ld] = f2tf32(va1.w);
            uint4 w = make_uint4(f2tf32(vb.x), f2tf32(vb.y), f2tf32(vb.z), f2tf32(vb.w));
            *(uint4*)&Bs[nbuf][kb_ld * LDB_S + nb_ld] = w;
        }
        __syncthreads();
    }

    // epilogue
    const int mb = warp_m * 32;
    const int nb = warp_n * 32;
#pragma unroll
    for (int im = 0; im < 2; im++) {
#pragma unroll
        for (int in = 0; in < 4; in++) {
            const int row = m0 + mb + im * 16 + g;
            const int col = n0 + nb + in * 8 + tig * 2;
            float bx = 0.f, by = 0.f;
            if (bias) { bx = bias[col]; by = bias[col + 1]; }
            float2 o0 = make_float2(acc[im][in][0] + bx, acc[im][in][1] + by);
            float2 o1 = make_float2(acc[im][in][2] + bx, acc[im][in][3] + by);
            *(float2*)&Cp[(long)row * N + col] = o0;
            *(float2*)&Cp[(long)(row + 8) * N + col] = o1;
        }
    }
}

// ---------------------------------------------------------------------------
// score[b,t,s] = sum_d v[d] * tanh(wq[b,t,d] + uh[b,s,d])   (MUFU-bound)
// ---------------------------------------------------------------------------
__global__ __launch_bounds__(256) void score_kernel(
    const float* __restrict__ wq, const float* __restrict__ uh,
    const float* __restrict__ v, float* __restrict__ sc)
{
    __shared__ float Aq[32][33];
    __shared__ float Au[32][33];
    __shared__ float vs[32];

    const int b = blockIdx.z;
    const int t0 = blockIdx.y * 32;
    const int s0 = blockIdx.x * 32;
    const int tid = threadIdx.x;
    const int tx = tid & 15, ty = tid >> 4;

    const float* wqb = wq + ((long)b * Tdim + t0) * Ddim;
    const float* uhb = uh + ((long)b * Sdim + s0) * Ddim;

    const int lr = tid >> 3;
    const int lc = (tid & 7) << 2;

    float acc00 = 0.f, acc01 = 0.f, acc10 = 0.f, acc11 = 0.f;

    for (int d0 = 0; d0 < Ddim; d0 += 32) {
        float4 q = *(const float4*)&wqb[(long)lr * Ddim + d0 + lc];
        Aq[lc + 0][lr] = q.x;
        Aq[lc + 1][lr] = q.y;
        Aq[lc + 2][lr] = q.z;
        Aq[lc + 3][lr] = q.w;
        float4 u = *(const float4*)&uhb[(long)lr * Ddim + d0 + lc];
        Au[lc + 0][lr] = u.x;
        Au[lc + 1][lr] = u.y;
        Au[lc + 2][lr] = u.z;
        Au[lc + 3][lr] = u.w;
        if (tid < 32) vs[tid] = v[d0 + tid];
        __syncthreads();

#pragma unroll
        for (int dk = 0; dk < 32; dk++) {
            float vv = vs[dk];
            float a0 = Aq[dk][ty * 2 + 0];
            float a1 = Aq[dk][ty * 2 + 1];
            float u0 = Au[dk][tx * 2 + 0];
            float u1 = Au[dk][tx * 2 + 1];
            acc00 += vv * tanh_fast(a0 + u0);
            acc01 += vv * tanh_fast(a0 + u1);
            acc10 += vv * tanh_fast(a1 + u0);
            acc11 += vv * tanh_fast(a1 + u1);
        }
        __syncthreads();
    }

    float* scp = sc + ((long)b * Tdim + t0) * Sdim + s0;
    scp[(long)(ty * 2 + 0) * Sdim + tx * 2 + 0] = acc00;
    scp[(long)(ty * 2 + 0) * Sdim + tx * 2 + 1] = acc01;
    scp[(long)(ty * 2 + 1) * Sdim + tx * 2 + 0] = acc10;
    scp[(long)(ty * 2 + 1) * Sdim + tx * 2 + 1] = acc11;
}

// ---------------------------------------------------------------------------
// Masked softmax per (b,t) row (reference semantics)
// ---------------------------------------------------------------------------
__global__ __launch_bounds__(256) void softmax_kernel(
    float* __restrict__ sc, const int* __restrict__ mask,
    float* __restrict__ attn_out)
{
    __shared__ float sm[8];
    __shared__ float ss[8];

    const int row = blockIdx.x;
    const int b = row / Tdim;
    const int s = threadIdx.x;
    const long idx = (long)row * Sdim + s;

    float x = sc[idx];

    float m = x;
#pragma unroll
    for (int o = 16; o > 0; o >>= 1)
        m = fmaxf(m, __shfl_xor_sync(0xffffffffu, m, o));
    const int warp = s >> 5, lane = s & 31;
    if (lane == 0) sm[warp] = m;
    __syncthreads();
    float mx = sm[0];
#pragma unroll
    for (int w = 1; w < 8; w++) mx = fmaxf(mx, sm[w]);

    const float keep = 1.0f - (float)mask[b * Sdim + s];
    const float e = __expf(x - mx) * keep;

    float t = e;
#pragma unroll
    for (int o = 16; o > 0; o >>= 1)
        t += __shfl_xor_sync(0xffffffffu, t, o);
    if (lane == 0) ss[warp] = t;
    __syncthreads();
    float sum = ss[0];
#pragma unroll
    for (int w = 1; w < 8; w++) sum += ss[w];

    const float a = e / sum;
    sc[idx] = a;
    if (attn_out) attn_out[idx] = a;
}

// ---------------------------------------------------------------------------
extern "C" void kernel_launch(void* const* d_in, const int* in_sizes, int n_in,
                              void* d_out, int out_size)
{
    const float* out_in = (const float*)d_in[0];  // (B,T,D)
    const float* ctx    = (const float*)d_in[1];  // (B,S,D)
    const int*   mask   = (const int*)d_in[2];    // (B,S)
    const float* Wq     = (const float*)d_in[3];  // (D,D)
    const float* bq     = (const float*)d_in[4];  // (D,)
    const float* Wc     = (const float*)d_in[5];  // (D,D)
    const float* v      = (const float*)d_in[6];  // (D,)
    const float* Wout   = (const float*)d_in[7];  // (2D,D)
    const float* bout   = (const float*)d_in[8];  // (D,)

    float *p_wq, *p_uh, *p_sc, *p_mix;
    cudaGetSymbolAddress((void**)&p_wq, g_wq);
    cudaGetSymbolAddress((void**)&p_uh, g_uh);
    cudaGetSymbolAddress((void**)&p_sc, g_sc);
    cudaGetSymbolAddress((void**)&p_mix, g_mix);

    const long BTD = (long)Bdim * Tdim * Ddim;  // 524288
    const long BTS = (long)Bdim * Tdim * Sdim;  // 262144
    float* out_f = (float*)d_out;
    float* attn_out = ((long)out_size >= BTD + BTS) ? (out_f + BTD) : nullptr;

    dim3 blk(256);

    // 1) wq = output @ Wq + bq   (1024 x 512, K=512)
    mma_gemm<<<dim3(Ddim / 64, (Bdim * Tdim) / 128, 1), blk>>>(
        out_in, out_in, Ddim, Wq, bq, p_wq, Bdim * Tdim, Ddim, Ddim, 0, 0, 0);

    // 2) uh = context @ Wc       (1024 x 512, K=512)
    mma_gemm<<<dim3(Ddim / 64, (Bdim * Sdim) / 128, 1), blk>>>(
        ctx, ctx, Ddim, Wc, nullptr, p_uh, Bdim * Sdim, Ddim, Ddim, 0, 0, 0);

    // 3) score
    score_kernel<<<dim3(Sdim / 32, Tdim / 32, Bdim), blk>>>(p_wq, p_uh, v, p_sc);

    // 4) masked softmax
    softmax_kernel<<<Bdim * Tdim, Sdim>>>(p_sc, mask, attn_out);

    // 5) mix = attn @ context    (batched 256 x 512, K=256)
    mma_gemm<<<dim3(Ddim / 64, Tdim / 128, Bdim), blk>>>(
        p_sc, p_sc, Sdim, ctx, nullptr, p_mix, Tdim, Ddim, Sdim,
        (long)Tdim * Sdim, (long)Sdim * Ddim, (long)Tdim * Ddim);

    // 6) out = [mix | output] @ Wout + bout  (1024 x 512, K=1024 concat)
    mma_gemm<<<dim3(Ddim / 64, (Bdim * Tdim) / 128, 1), blk>>>(
        p_mix, out_in, Ddim, Wout, bout, out_f, Bdim * Tdim, Ddim, 2 * Ddim, 0, 0, 0);
}

// round 4
// speedup vs baseline: 1.6569x; 1.5391x over previous
#include <cuda_runtime.h>
#include <cstdint>

#define Bdim 4
#define Tdim 256
#define Sdim 256
#define Ddim 512

// Scratch (allocation-free rule: __device__ globals)
__device__ float g_wq[Bdim * Tdim * Ddim];   // 2 MB
__device__ float g_uh[Bdim * Sdim * Ddim];   // 2 MB
__device__ float g_sc[Bdim * Tdim * Sdim];   // 1 MB (scores, then attn in-place)
__device__ float g_mix[Bdim * Tdim * Ddim];  // 2 MB

__device__ __forceinline__ float tanh_fast(float x) {
    float y;
    asm("tanh.approx.f32 %0, %1;" : "=f"(y) : "f"(x));
    return y;
}

__device__ __forceinline__ uint32_t f2tf32(float x) {
    uint32_t y;
    asm("cvt.rna.tf32.f32 %0, %1;" : "=r"(y) : "f"(x));
    return y;
}

__device__ __forceinline__ void mma_tf32(float* d, const uint32_t* a,
                                         const uint32_t* b) {
    asm volatile(
        "mma.sync.aligned.m16n8k8.row.col.f32.tf32.tf32.f32 "
        "{%0,%1,%2,%3}, {%4,%5,%6,%7}, {%8,%9}, {%0,%1,%2,%3};"
        : "+f"(d[0]), "+f"(d[1]), "+f"(d[2]), "+f"(d[3])
        : "r"(a[0]), "r"(a[1]), "r"(a[2]), "r"(a[3]), "r"(b[0]), "r"(b[1]));
}

#define CP16(dst, src) \
    asm volatile("cp.async.cg.shared.global [%0], [%1], 16;" \
                 :: "r"(dst), "l"(src) : "memory")
#define CP_COMMIT() asm volatile("cp.async.commit_group;" ::: "memory")
#define CP_WAIT1()  asm volatile("cp.async.wait_group 1;" ::: "memory")

// ---------------------------------------------------------------------------
// tf32 mma.sync GEMM, cp.async 3-stage pipeline.
// C[M,N] = concat_k(A1,A2)[M,K] @ B[K,N] (+bias)
// Block tile 128(M) x 64(N), BK=16, 256 threads = 8 warps (4m x 2n),
// warp tile 32x32 (2x4 frags of m16n8k8). A smem [m][k] pad->20 words,
// B smem [k][n] pad->72 words (both conflict-free & 16B-chunk aligned).
// dual=1: blockIdx.z==1 switches to job (A1d,Bmd,biasd,Cd) (no batch).
// dual=0: blockIdx.z batches with strides sA,sB,sC.
// ---------------------------------------------------------------------------
#define STAGES 3
#define LDA 20
#define LDB 72

__global__ __launch_bounds__(256) void mma_gemm(
    const float* __restrict__ A1, const float* __restrict__ A2, int Ksplit,
    const float* __restrict__ Bm, const float* __restrict__ bias,
    float* __restrict__ C,
    const float* __restrict__ A1d, const float* __restrict__ Bmd,
    const float* __restrict__ biasd, float* __restrict__ Cd,
    int dual, int N, int K, long sA, long sB, long sC)
{
    __shared__ float As[STAGES][128 * LDA];  // 10240 B/stage
    __shared__ float Bs[STAGES][16 * LDB];   //  4608 B/stage

    const int tid = threadIdx.x;
    const int wid = tid >> 5;
    const int lane = tid & 31;
    const int g = lane >> 2;
    const int tig = lane & 3;
    const int warp_m = wid >> 1;
    const int warp_n = wid & 1;
    const int z = blockIdx.z;

    const float* A1p;
    const float* A2p;
    const float* Bp;
    const float* biasp;
    float* Cp;
    int ksp = Ksplit;
    if (dual && z == 1) {
        A1p = A1d; A2p = A1d; Bp = Bmd; biasp = biasd; Cp = Cd; ksp = K;
    } else {
        A1p = A1 + (long)z * sA; A2p = A2 + (long)z * sA;
        Bp = Bm + (long)z * sB; biasp = bias; Cp = C + (long)z * sC;
    }
    const int ldA1 = ksp;
    const int ldA2 = K - ksp;

    const int m0 = blockIdx.y * 128;
    const int n0 = blockIdx.x * 64;

    // cp.async mapping
    const int ar = tid >> 2;           // A row 0..63 (+64 for 2nd chunk)
    const int akc = (tid & 3) << 2;    // A k offset {0,4,8,12}
    const int bkr = tid >> 4;          // B k-row 0..15
    const int bnc = (tid & 15) << 2;   // B n offset 0..60

    uint32_t as_s = (uint32_t)__cvta_generic_to_shared(&As[0][0]);
    uint32_t bs_s = (uint32_t)__cvta_generic_to_shared(&Bs[0][0]);
    const uint32_t ABYTES = 128 * LDA * 4;
    const uint32_t BBYTES = 16 * LDB * 4;

    const int NT = K >> 4;

    float acc[2][4][4];
#pragma unroll
    for (int i = 0; i < 2; i++)
#pragma unroll
        for (int j = 0; j < 4; j++)
#pragma unroll
            for (int q = 0; q < 4; q++) acc[i][j][q] = 0.f;

    // tile issue helper (inlined manually via lambda)
    auto issue = [&](int stage, int kt) {
        const int kg = kt << 4;
        const float* abase;
        int lda_, koff;
        if (kg < ksp) { abase = A1p; lda_ = ldA1; koff = kg; }
        else          { abase = A2p; lda_ = ldA2; koff = kg - ksp; }
        const float* s0 = abase + (long)(m0 + ar) * lda_ + koff + akc;
        const float* s1 = s0 + (long)64 * lda_;
        uint32_t d0 = as_s + stage * ABYTES + (ar * LDA + akc) * 4;
        CP16(d0, s0);
        CP16(d0 + 64 * LDA * 4, s1);
        const float* sb = Bp + (long)(kg + bkr) * N + n0 + bnc;
        uint32_t db = bs_s + stage * BBYTES + (bkr * LDB + bnc) * 4;
        CP16(db, sb);
    };

    // prologue: stages 0..STAGES-2
#pragma unroll
    for (int p = 0; p < STAGES - 1; p++) {
        issue(p, p);
        CP_COMMIT();
    }

    for (int t = 0; t < NT; t++) {
        const int st = t % STAGES;
        CP_WAIT1();
        __syncthreads();

        if (t + STAGES - 1 < NT) issue((t + STAGES - 1) % STAGES, t + STAGES - 1);
        CP_COMMIT();

        const float* as = As[st];
        const float* bs = Bs[st];
        const int mb = warp_m * 32;
        const int nb = warp_n * 32;
#pragma unroll
        for (int ks = 0; ks < 2; ks++) {
            const int k0 = ks << 3;
            uint32_t a[2][4], b[4][2];
#pragma unroll
            for (int im = 0; im < 2; im++) {
                const float* ap = as + (mb + im * 16 + g) * LDA;
                a[im][0] = f2tf32(ap[k0 + tig]);
                a[im][1] = f2tf32(ap[8 * LDA + k0 + tig]);
                a[im][2] = f2tf32(ap[k0 + tig + 4]);
                a[im][3] = f2tf32(ap[8 * LDA + k0 + tig + 4]);
            }
#pragma unroll
            for (int in = 0; in < 4; in++) {
                const int nc = nb + in * 8 + g;
                b[in][0] = f2tf32(bs[(k0 + tig) * LDB + nc]);
                b[in][1] = f2tf32(bs[(k0 + tig + 4) * LDB + nc]);
            }
#pragma unroll
            for (int im = 0; im < 2; im++)
#pragma unroll
                for (int in = 0; in < 4; in++)
                    mma_tf32(acc[im][in], a[im], b[in]);
        }
        __syncthreads();
    }

    // epilogue
    const int mb = warp_m * 32;
    const int nb = warp_n * 32;
#pragma unroll
    for (int im = 0; im < 2; im++) {
#pragma unroll
        for (int in = 0; in < 4; in++) {
            const int row = m0 + mb + im * 16 + g;
            const int col = n0 + nb + in * 8 + tig * 2;
            float bx = 0.f, by = 0.f;
            if (biasp) { bx = biasp[col]; by = biasp[col + 1]; }
            float2 o0 = make_float2(acc[im][in][0] + bx, acc[im][in][1] + by);
            float2 o1 = make_float2(acc[im][in][2] + bx, acc[im][in][3] + by);
            *(float2*)&Cp[(long)row * N + col] = o0;
            *(float2*)&Cp[(long)(row + 8) * N + col] = o1;
        }
    }
}

// ---------------------------------------------------------------------------
// score[b,t,s] = sum_d v[d] * tanh(wq[b,t,d] + uh[b,s,d])   (MUFU-bound)
// ---------------------------------------------------------------------------
__global__ __launch_bounds__(256) void score_kernel(
    const float* __restrict__ wq, const float* __restrict__ uh,
    const float* __restrict__ v, float* __restrict__ sc)
{
    __shared__ float Aq[32][33];
    __shared__ float Au[32][33];
    __shared__ float vs[32];

    const int b = blockIdx.z;
    const int t0 = blockIdx.y * 32;
    const int s0 = blockIdx.x * 32;
    const int tid = threadIdx.x;
    const int tx = tid & 15, ty = tid >> 4;

    const float* wqb = wq + ((long)b * Tdim + t0) * Ddim;
    const float* uhb = uh + ((long)b * Sdim + s0) * Ddim;

    const int lr = tid >> 3;
    const int lc = (tid & 7) << 2;

    float acc00 = 0.f, acc01 = 0.f, acc10 = 0.f, acc11 = 0.f;

    for (int d0 = 0; d0 < Ddim; d0 += 32) {
        float4 q = *(const float4*)&wqb[(long)lr * Ddim + d0 + lc];
        Aq[lc + 0][lr] = q.x;
        Aq[lc + 1][lr] = q.y;
        Aq[lc + 2][lr] = q.z;
        Aq[lc + 3][lr] = q.w;
        float4 u = *(const float4*)&uhb[(long)lr * Ddim + d0 + lc];
        Au[lc + 0][lr] = u.x;
        Au[lc + 1][lr] = u.y;
        Au[lc + 2][lr] = u.z;
        Au[lc + 3][lr] = u.w;
        if (tid < 32) vs[tid] = v[d0 + tid];
        __syncthreads();

#pragma unroll
        for (int dk = 0; dk < 32; dk++) {
            float vv = vs[dk];
            float a0 = Aq[dk][ty * 2 + 0];
            float a1 = Aq[dk][ty * 2 + 1];
            float u0 = Au[dk][tx * 2 + 0];
            float u1 = Au[dk][tx * 2 + 1];
            acc00 += vv * tanh_fast(a0 + u0);
            acc01 += vv * tanh_fast(a0 + u1);
            acc10 += vv * tanh_fast(a1 + u0);
            acc11 += vv * tanh_fast(a1 + u1);
        }
        __syncthreads();
    }

    float* scp = sc + ((long)b * Tdim + t0) * Sdim + s0;
    scp[(long)(ty * 2 + 0) * Sdim + tx * 2 + 0] = acc00;
    scp[(long)(ty * 2 + 0) * Sdim + tx * 2 + 1] = acc01;
    scp[(long)(ty * 2 + 1) * Sdim + tx * 2 + 0] = acc10;
    scp[(long)(ty * 2 + 1) * Sdim + tx * 2 + 1] = acc11;
}

// ---------------------------------------------------------------------------
// Masked softmax per (b,t) row (reference semantics)
// ---------------------------------------------------------------------------
__global__ __launch_bounds__(256) void softmax_kernel(
    float* __restrict__ sc, const int* __restrict__ mask,
    float* __restrict__ attn_out)
{
    __shared__ float sm[8];
    __shared__ float ss[8];

    const int row = blockIdx.x;
    const int b = row / Tdim;
    const int s = threadIdx.x;
    const long idx = (long)row * Sdim + s;

    float x = sc[idx];

    float m = x;
#pragma unroll
    for (int o = 16; o > 0; o >>= 1)
        m = fmaxf(m, __shfl_xor_sync(0xffffffffu, m, o));
    const int warp = s >> 5, lane = s & 31;
    if (lane == 0) sm[warp] = m;
    __syncthreads();
    float mx = sm[0];
#pragma unroll
    for (int w = 1; w < 8; w++) mx = fmaxf(mx, sm[w]);

    const float keep = 1.0f - (float)mask[b * Sdim + s];
    const float e = __expf(x - mx) * keep;

    float t = e;
#pragma unroll
    for (int o = 16; o > 0; o >>= 1)
        t += __shfl_xor_sync(0xffffffffu, t, o);
    if (lane == 0) ss[warp] = t;
    __syncthreads();
    float sum = ss[0];
#pragma unroll
    for (int w = 1; w < 8; w++) sum += ss[w];

    const float a = e / sum;
    sc[idx] = a;
    if (attn_out) attn_out[idx] = a;
}

// ---------------------------------------------------------------------------
extern "C" void kernel_launch(void* const* d_in, const int* in_sizes, int n_in,
                              void* d_out, int out_size)
{
    const float* out_in = (const float*)d_in[0];  // (B,T,D)
    const float* ctx    = (const float*)d_in[1];  // (B,S,D)
    const int*   mask   = (const int*)d_in[2];    // (B,S)
    const float* Wq     = (const float*)d_in[3];  // (D,D)
    const float* bq     = (const float*)d_in[4];  // (D,)
    const float* Wc     = (const float*)d_in[5];  // (D,D)
    const float* v      = (const float*)d_in[6];  // (D,)
    const float* Wout   = (const float*)d_in[7];  // (2D,D)
    const float* bout   = (const float*)d_in[8];  // (D,)

    float *p_wq, *p_uh, *p_sc, *p_mix;
    cudaGetSymbolAddress((void**)&p_wq, g_wq);
    cudaGetSymbolAddress((void**)&p_uh, g_uh);
    cudaGetSymbolAddress((void**)&p_sc, g_sc);
    cudaGetSymbolAddress((void**)&p_mix, g_mix);

    const long BTD = (long)Bdim * Tdim * Ddim;  // 524288
    const long BTS = (long)Bdim * Tdim * Sdim;  // 262144
    float* out_f = (float*)d_out;
    float* attn_out = ((long)out_size >= BTD + BTS) ? (out_f + BTD) : nullptr;

    dim3 blk(256);

    // 1) fused projections: z=0 -> wq = output@Wq+bq; z=1 -> uh = context@Wc
    mma_gemm<<<dim3(Ddim / 64, (Bdim * Tdim) / 128, 2), blk>>>(
        out_in, out_in, Ddim, Wq, bq, p_wq,
        ctx, Wc, nullptr, p_uh,
        1, Ddim, Ddim, 0, 0, 0);

    // 2) score
    score_kernel<<<dim3(Sdim / 32, Tdim / 32, Bdim), blk>>>(p_wq, p_uh, v, p_sc);

    // 3) masked softmax
    softmax_kernel<<<Bdim * Tdim, Sdim>>>(p_sc, mask, attn_out);

    // 4) mix = attn @ context   (batched 256 x 512, K=256)
    mma_gemm<<<dim3(Ddim / 64, Tdim / 128, Bdim), blk>>>(
        p_sc, p_sc, Sdim, ctx, nullptr, p_mix,
        nullptr, nullptr, nullptr, nullptr,
        0, Ddim, Sdim, (long)Tdim * Sdim, (long)Sdim * Ddim, (long)Tdim * Ddim);

    // 5) out = [mix | output] @ Wout + bout  (1024 x 512, K=1024 concat)
    mma_gemm<<<dim3(Ddim / 64, (Bdim * Tdim) / 128, 1), blk>>>(
        p_mix, out_in, Ddim, Wout, bout, out_f,
        nullptr, nullptr, nullptr, nullptr,
        0, Ddim, 2 * Ddim, 0, 0, 0);
}

// round 5
// speedup vs baseline: 2.0754x; 1.2525x over previous
#include <cuda_runtime.h>
#include <cstdint>

#define Bdim 4
#define Tdim 256
#define Sdim 256
#define Ddim 512

// Scratch (allocation-free rule: __device__ globals)
__device__ float g_wq[Bdim * Tdim * Ddim];    // 2 MB
__device__ float g_uh[Bdim * Sdim * Ddim];    // 2 MB
__device__ float g_sc[Bdim * Tdim * Sdim];    // 1 MB (scores, then attn)
__device__ float g_pre1[Bdim * Sdim * Ddim];  // 2 MB  ctx @ Wout_top
__device__ float g_pre2[Bdim * Tdim * Ddim];  // 2 MB  output @ Wout_bot + bout

__device__ __forceinline__ float tanh_fast(float x) {
    float y;
    asm("tanh.approx.f32 %0, %1;" : "=f"(y) : "f"(x));
    return y;
}

__device__ __forceinline__ uint32_t f2tf32(float x) {
    uint32_t y;
    asm("cvt.rna.tf32.f32 %0, %1;" : "=r"(y) : "f"(x));
    return y;
}

__device__ __forceinline__ void mma_tf32(float* d, const uint32_t* a,
                                         const uint32_t* b) {
    asm volatile(
        "mma.sync.aligned.m16n8k8.row.col.f32.tf32.tf32.f32 "
        "{%0,%1,%2,%3}, {%4,%5,%6,%7}, {%8,%9}, {%0,%1,%2,%3};"
        : "+f"(d[0]), "+f"(d[1]), "+f"(d[2]), "+f"(d[3])
        : "r"(a[0]), "r"(a[1]), "r"(a[2]), "r"(a[3]), "r"(b[0]), "r"(b[1]));
}

#define CP16(dst, src) \
    asm volatile("cp.async.cg.shared.global [%0], [%1], 16;" \
                 :: "r"(dst), "l"(src) : "memory")
#define CP_COMMIT() asm volatile("cp.async.commit_group;" ::: "memory")
#define CP_WAIT2()  asm volatile("cp.async.wait_group 2;" ::: "memory")

// ---------------------------------------------------------------------------
// Shared tf32 mma.sync GEMM core: 64x64 block tile, 128 threads (2x2 warps,
// warp tile 32x32), BK=16, 4-stage cp.async pipeline.
// C[m0:m0+64, n0:n0+64] = A[M,K](lda) @ B[K,N] (+bias[n]) (+addend[m,n])
// ---------------------------------------------------------------------------
#define STAGES 4
#define LDA 20
#define LDB 72
#define ABYTES (64 * LDA * 4)
#define BBYTES (16 * LDB * 4)

__device__ __forceinline__ void gemm_core(
    const float* __restrict__ A, int lda,
    const float* __restrict__ B, int ldb, int K,
    const float* __restrict__ bias, const float* __restrict__ addend,
    float* __restrict__ C, int N, int m0, int n0)
{
    __shared__ float As[STAGES][64 * LDA];
    __shared__ float Bs[STAGES][16 * LDB];

    const int tid = threadIdx.x;
    const int wid = tid >> 5;
    const int lane = tid & 31;
    const int g = lane >> 2;
    const int tig = lane & 3;
    const int warp_m = wid >> 1;
    const int warp_n = wid & 1;

    const int ar = tid >> 1;          // 0..63
    const int ak = (tid & 1) << 3;    // 0 or 8
    const int br = tid >> 3;          // 0..15
    const int bc = (tid & 7) << 3;    // 0..56

    uint32_t as_s = (uint32_t)__cvta_generic_to_shared(&As[0][0]);
    uint32_t bs_s = (uint32_t)__cvta_generic_to_shared(&Bs[0][0]);

    const int NT = K >> 4;

    float acc[2][4][4];
#pragma unroll
    for (int i = 0; i < 2; i++)
#pragma unroll
        for (int j = 0; j < 4; j++)
#pragma unroll
            for (int q = 0; q < 4; q++) acc[i][j][q] = 0.f;

    auto issue = [&](int stage, int kt) {
        const int kg = kt << 4;
        const float* s0 = A + (long)(m0 + ar) * lda + kg + ak;
        uint32_t d0 = as_s + stage * ABYTES + (ar * LDA + ak) * 4;
        CP16(d0, s0);
        CP16(d0 + 16, s0 + 4);
        const float* sb = B + (long)(kg + br) * ldb + n0 + bc;
        uint32_t db = bs_s + stage * BBYTES + (br * LDB + bc) * 4;
        CP16(db, sb);
        CP16(db + 16, sb + 4);
    };

#pragma unroll
    for (int p = 0; p < STAGES - 1; p++) {
        if (p < NT) issue(p, p);
        CP_COMMIT();
    }

    for (int t = 0; t < NT; t++) {
        const int st = t & (STAGES - 1);
        CP_WAIT2();
        __syncthreads();

        if (t + STAGES - 1 < NT) issue((t + STAGES - 1) & (STAGES - 1), t + STAGES - 1);
        CP_COMMIT();

        const float* as = As[st];
        const float* bs = Bs[st];
        const int mb = warp_m * 32;
        const int nb = warp_n * 32;
#pragma unroll
        for (int ks = 0; ks < 2; ks++) {
            const int k0 = ks << 3;
            uint32_t a[2][4], b[4][2];
#pragma unroll
            for (int im = 0; im < 2; im++) {
                const float* ap = as + (mb + im * 16 + g) * LDA;
                a[im][0] = f2tf32(ap[k0 + tig]);
                a[im][1] = f2tf32(ap[8 * LDA + k0 + tig]);
                a[im][2] = f2tf32(ap[k0 + tig + 4]);
                a[im][3] = f2tf32(ap[8 * LDA + k0 + tig + 4]);
            }
#pragma unroll
            for (int in = 0; in < 4; in++) {
                const int nc = nb + in * 8 + g;
                b[in][0] = f2tf32(bs[(k0 + tig) * LDB + nc]);
                b[in][1] = f2tf32(bs[(k0 + tig + 4) * LDB + nc]);
            }
#pragma unroll
            for (int im = 0; im < 2; im++)
#pragma unroll
                for (int in = 0; in < 4; in++)
                    mma_tf32(acc[im][in], a[im], b[in]);
        }
        __syncthreads();
    }

    const int mb = warp_m * 32;
    const int nb = warp_n * 32;
#pragma unroll
    for (int im = 0; im < 2; im++) {
#pragma unroll
        for (int in = 0; in < 4; in++) {
            const int row = m0 + mb + im * 16 + g;
            const int col = n0 + nb + in * 8 + tig * 2;
            float bx = 0.f, by = 0.f;
            if (bias) { bx = bias[col]; by = bias[col + 1]; }
            float2 o0 = make_float2(acc[im][in][0] + bx, acc[im][in][1] + by);
            float2 o1 = make_float2(acc[im][in][2] + bx, acc[im][in][3] + by);
            if (addend) {
                const float2 r0 = *(const float2*)&addend[(long)row * N + col];
                const float2 r1 = *(const float2*)&addend[(long)(row + 8) * N + col];
                o0.x += r0.x; o0.y += r0.y;
                o1.x += r1.x; o1.y += r1.y;
            }
            *(float2*)&C[(long)row * N + col] = o0;
            *(float2*)&C[(long)(row + 8) * N + col] = o1;
        }
    }
}

// Four independent 1024x512x512 jobs selected by blockIdx.z
struct Job {
    const float* A;
    const float* B;
    const float* bias;
    float* C;
};

__global__ __launch_bounds__(128) void gemm4(Job j0, Job j1, Job j2, Job j3)
{
    Job j = (blockIdx.z == 0) ? j0 : (blockIdx.z == 1) ? j1
          : (blockIdx.z == 2) ? j2 : j3;
    gemm_core(j.A, Ddim, j.B, Ddim, Ddim, j.bias, nullptr, j.C, Ddim,
              blockIdx.y * 64, blockIdx.x * 64);
}

// Final: out[b] = attn[b] @ pre1[b] + pre2[b]   (256 x 512, K=256 per batch)
__global__ __launch_bounds__(128) void gemm_fin(
    const float* __restrict__ attn, const float* __restrict__ pre1,
    const float* __restrict__ pre2, float* __restrict__ out)
{
    const int z = blockIdx.z;
    gemm_core(attn + (long)z * Tdim * Sdim, Sdim,
              pre1 + (long)z * Sdim * Ddim, Ddim, Sdim,
              nullptr, pre2 + (long)z * Tdim * Ddim,
              out + (long)z * Tdim * Ddim, Ddim,
              blockIdx.y * 64, blockIdx.x * 64);
}

// ---------------------------------------------------------------------------
// score[b,t,s] = sum_d v[d] * tanh(wq[b,t,d] + uh[b,s,d])   (MUFU-bound)
// ---------------------------------------------------------------------------
__global__ __launch_bounds__(256) void score_kernel(
    const float* __restrict__ wq, const float* __restrict__ uh,
    const float* __restrict__ v, float* __restrict__ sc)
{
    __shared__ float Aq[32][33];
    __shared__ float Au[32][33];
    __shared__ float vs[32];

    const int b = blockIdx.z;
    const int t0 = blockIdx.y * 32;
    const int s0 = blockIdx.x * 32;
    const int tid = threadIdx.x;
    const int tx = tid & 15, ty = tid >> 4;

    const float* wqb = wq + ((long)b * Tdim + t0) * Ddim;
    const float* uhb = uh + ((long)b * Sdim + s0) * Ddim;

    const int lr = tid >> 3;
    const int lc = (tid & 7) << 2;

    float acc00 = 0.f, acc01 = 0.f, acc10 = 0.f, acc11 = 0.f;

    for (int d0 = 0; d0 < Ddim; d0 += 32) {
        float4 q = *(const float4*)&wqb[(long)lr * Ddim + d0 + lc];
        Aq[lc + 0][lr] = q.x;
        Aq[lc + 1][lr] = q.y;
        Aq[lc + 2][lr] = q.z;
        Aq[lc + 3][lr] = q.w;
        float4 u = *(const float4*)&uhb[(long)lr * Ddim + d0 + lc];
        Au[lc + 0][lr] = u.x;
        Au[lc + 1][lr] = u.y;
        Au[lc + 2][lr] = u.z;
        Au[lc + 3][lr] = u.w;
        if (tid < 32) vs[tid] = v[d0 + tid];
        __syncthreads();

#pragma unroll
        for (int dk = 0; dk < 32; dk++) {
            float vv = vs[dk];
            float a0 = Aq[dk][ty * 2 + 0];
            float a1 = Aq[dk][ty * 2 + 1];
            float u0 = Au[dk][tx * 2 + 0];
            float u1 = Au[dk][tx * 2 + 1];
            acc00 += vv * tanh_fast(a0 + u0);
            acc01 += vv * tanh_fast(a0 + u1);
            acc10 += vv * tanh_fast(a1 + u0);
            acc11 += vv * tanh_fast(a1 + u1);
        }
        __syncthreads();
    }

    float* scp = sc + ((long)b * Tdim + t0) * Sdim + s0;
    scp[(long)(ty * 2 + 0) * Sdim + tx * 2 + 0] = acc00;
    scp[(long)(ty * 2 + 0) * Sdim + tx * 2 + 1] = acc01;
    scp[(long)(ty * 2 + 1) * Sdim + tx * 2 + 0] = acc10;
    scp[(long)(ty * 2 + 1) * Sdim + tx * 2 + 1] = acc11;
}

// ---------------------------------------------------------------------------
// Masked softmax per (b,t) row (reference semantics)
// ---------------------------------------------------------------------------
__global__ __launch_bounds__(256) void softmax_kernel(
    float* __restrict__ sc, const int* __restrict__ mask,
    float* __restrict__ attn_out)
{
    __shared__ float sm[8];
    __shared__ float ss[8];

    const int row = blockIdx.x;
    const int b = row / Tdim;
    const int s = threadIdx.x;
    const long idx = (long)row * Sdim + s;

    float x = sc[idx];

    float m = x;
#pragma unroll
    for (int o = 16; o > 0; o >>= 1)
        m = fmaxf(m, __shfl_xor_sync(0xffffffffu, m, o));
    const int warp = s >> 5, lane = s & 31;
    if (lane == 0) sm[warp] = m;
    __syncthreads();
    float mx = sm[0];
#pragma unroll
    for (int w = 1; w < 8; w++) mx = fmaxf(mx, sm[w]);

    const float keep = 1.0f - (float)mask[b * Sdim + s];
    const float e = __expf(x - mx) * keep;

    float t = e;
#pragma unroll
    for (int o = 16; o > 0; o >>= 1)
        t += __shfl_xor_sync(0xffffffffu, t, o);
    if (lane == 0) ss[warp] = t;
    __syncthreads();
    float sum = ss[0];
#pragma unroll
    for (int w = 1; w < 8; w++) sum += ss[w];

    const float a = e / sum;
    sc[idx] = a;
    if (attn_out) attn_out[idx] = a;
}

// ---------------------------------------------------------------------------
extern "C" void kernel_launch(void* const* d_in, const int* in_sizes, int n_in,
                              void* d_out, int out_size)
{
    const float* out_in = (const float*)d_in[0];  // (B,T,D)
    const float* ctx    = (const float*)d_in[1];  // (B,S,D)
    const int*   mask   = (const int*)d_in[2];    // (B,S)
    const float* Wq     = (const float*)d_in[3];  // (D,D)
    const float* bq     = (const float*)d_in[4];  // (D,)
    const float* Wc     = (const float*)d_in[5];  // (D,D)
    const float* v      = (const float*)d_in[6];  // (D,)
    const float* Wout   = (const float*)d_in[7];  // (2D,D)
    const float* bout   = (const float*)d_in[8];  // (D,)

    float *p_wq, *p_uh, *p_sc, *p_pre1, *p_pre2;
    cudaGetSymbolAddress((void**)&p_wq, g_wq);
    cudaGetSymbolAddress((void**)&p_uh, g_uh);
    cudaGetSymbolAddress((void**)&p_sc, g_sc);
    cudaGetSymbolAddress((void**)&p_pre1, g_pre1);
    cudaGetSymbolAddress((void**)&p_pre2, g_pre2);

    const long BTD = (long)Bdim * Tdim * Ddim;  // 524288
    const long BTS = (long)Bdim * Tdim * Sdim;  // 262144
    float* out_f = (float*)d_out;
    float* attn_out = ((long)out_size >= BTD + BTS) ? (out_f + BTD) : nullptr;

    // 1) Four fused 1024x512x512 GEMMs:
    //    z0: wq   = output @ Wq + bq
    //    z1: uh   = context @ Wc
    //    z2: pre1 = context @ Wout[0:D]          (top rows)
    //    z3: pre2 = output @ Wout[D:2D] + bout   (bottom rows)
    Job j0{out_in, Wq, bq, p_wq};
    Job j1{ctx, Wc, nullptr, p_uh};
    Job j2{ctx, Wout, nullptr, p_pre1};
    Job j3{out_in, Wout + (long)Ddim * Ddim, bout, p_pre2};
    gemm4<<<dim3(Ddim / 64, (Bdim * Tdim) / 64, 4), 128>>>(j0, j1, j2, j3);

    // 2) score
    score_kernel<<<dim3(Sdim / 32, Tdim / 32, Bdim), 256>>>(p_wq, p_uh, v, p_sc);

    // 3) masked softmax (attn in-place in g_sc, also to d_out attn region)
    softmax_kernel<<<Bdim * Tdim, Sdim>>>(p_sc, mask, attn_out);

    // 4) out = attn @ pre1 + pre2   (batched 256x512, K=256)
    gemm_fin<<<dim3(Ddim / 64, Tdim / 64, Bdim), 128>>>(p_sc, p_pre1, p_pre2, out_f);
}

// round 6
// speedup vs baseline: 2.1140x; 1.0186x over previous
#include <cuda_runtime.h>
#include <cstdint>

#define Bdim 4
#define Tdim 256
#define Sdim 256
#define Ddim 512

// Scratch (allocation-free rule: __device__ globals)
__device__ float g_wq[Bdim * Tdim * Ddim];    // 2 MB
__device__ float g_uh[Bdim * Sdim * Ddim];    // 2 MB
__device__ float g_sc[Bdim * Tdim * Sdim];    // 1 MB (scores, then attn)
__device__ float g_pre1[Bdim * Sdim * Ddim];  // 2 MB  ctx @ Wout_top
__device__ float g_pre2[Bdim * Tdim * Ddim];  // 2 MB  output @ Wout_bot + bout

__device__ __forceinline__ float tanh_fast(float x) {
    float y;
    asm("tanh.approx.f32 %0, %1;" : "=f"(y) : "f"(x));
    return y;
}

__device__ __forceinline__ uint32_t f2tf32(float x) {
    uint32_t y;
    asm("cvt.rna.tf32.f32 %0, %1;" : "=r"(y) : "f"(x));
    return y;
}

__device__ __forceinline__ void mma_tf32(float* d, const uint32_t* a,
                                         const uint32_t* b) {
    asm volatile(
        "mma.sync.aligned.m16n8k8.row.col.f32.tf32.tf32.f32 "
        "{%0,%1,%2,%3}, {%4,%5,%6,%7}, {%8,%9}, {%0,%1,%2,%3};"
        : "+f"(d[0]), "+f"(d[1]), "+f"(d[2]), "+f"(d[3])
        : "r"(a[0]), "r"(a[1]), "r"(a[2]), "r"(a[3]), "r"(b[0]), "r"(b[1]));
}

#define CP16(dst, src) \
    asm volatile("cp.async.cg.shared.global [%0], [%1], 16;" \
                 :: "r"(dst), "l"(src) : "memory")
#define CP_COMMIT() asm volatile("cp.async.commit_group;" ::: "memory")
#define CP_WAIT2()  asm volatile("cp.async.wait_group 2;" ::: "memory")

#define STAGES 4
#define LDA 20
#define LDB 72
#define ABYTES (64 * LDA * 4)
#define BBYTES (16 * LDB * 4)

// ---------------------------------------------------------------------------
// 128-thread core: 64x64 tile, 4 warps (2x2), warp tile 32x32. (gemm4)
// ---------------------------------------------------------------------------
__device__ __forceinline__ void gemm_core(
    const float* __restrict__ A, int lda,
    const float* __restrict__ B, int ldb, int K,
    const float* __restrict__ bias, const float* __restrict__ addend,
    float* __restrict__ C, int N, int m0, int n0)
{
    __shared__ float As[STAGES][64 * LDA];
    __shared__ float Bs[STAGES][16 * LDB];

    const int tid = threadIdx.x;
    const int wid = tid >> 5;
    const int lane = tid & 31;
    const int g = lane >> 2;
    const int tig = lane & 3;
    const int warp_m = wid >> 1;
    const int warp_n = wid & 1;

    const int ar = tid >> 1;
    const int ak = (tid & 1) << 3;
    const int br = tid >> 3;
    const int bc = (tid & 7) << 3;

    uint32_t as_s = (uint32_t)__cvta_generic_to_shared(&As[0][0]);
    uint32_t bs_s = (uint32_t)__cvta_generic_to_shared(&Bs[0][0]);

    const int NT = K >> 4;

    float acc[2][4][4];
#pragma unroll
    for (int i = 0; i < 2; i++)
#pragma unroll
        for (int j = 0; j < 4; j++)
#pragma unroll
            for (int q = 0; q < 4; q++) acc[i][j][q] = 0.f;

    auto issue = [&](int stage, int kt) {
        const int kg = kt << 4;
        const float* s0 = A + (long)(m0 + ar) * lda + kg + ak;
        uint32_t d0 = as_s + stage * ABYTES + (ar * LDA + ak) * 4;
        CP16(d0, s0);
        CP16(d0 + 16, s0 + 4);
        const float* sb = B + (long)(kg + br) * ldb + n0 + bc;
        uint32_t db = bs_s + stage * BBYTES + (br * LDB + bc) * 4;
        CP16(db, sb);
        CP16(db + 16, sb + 4);
    };

#pragma unroll
    for (int p = 0; p < STAGES - 1; p++) {
        if (p < NT) issue(p, p);
        CP_COMMIT();
    }

    for (int t = 0; t < NT; t++) {
        const int st = t & (STAGES - 1);
        CP_WAIT2();
        __syncthreads();

        if (t + STAGES - 1 < NT) issue((t + STAGES - 1) & (STAGES - 1), t + STAGES - 1);
        CP_COMMIT();

        const float* as = As[st];
        const float* bs = Bs[st];
        const int mb = warp_m * 32;
        const int nb = warp_n * 32;
#pragma unroll
        for (int ks = 0; ks < 2; ks++) {
            const int k0 = ks << 3;
            uint32_t a[2][4], b[4][2];
#pragma unroll
            for (int im = 0; im < 2; im++) {
                const float* ap = as + (mb + im * 16 + g) * LDA;
                a[im][0] = f2tf32(ap[k0 + tig]);
                a[im][1] = f2tf32(ap[8 * LDA + k0 + tig]);
                a[im][2] = f2tf32(ap[k0 + tig + 4]);
                a[im][3] = f2tf32(ap[8 * LDA + k0 + tig + 4]);
            }
#pragma unroll
            for (int in = 0; in < 4; in++) {
                const int nc = nb + in * 8 + g;
                b[in][0] = f2tf32(bs[(k0 + tig) * LDB + nc]);
                b[in][1] = f2tf32(bs[(k0 + tig + 4) * LDB + nc]);
            }
#pragma unroll
            for (int im = 0; im < 2; im++)
#pragma unroll
                for (int in = 0; in < 4; in++)
                    mma_tf32(acc[im][in], a[im], b[in]);
        }
        __syncthreads();
    }

    const int mb = warp_m * 32;
    const int nb = warp_n * 32;
#pragma unroll
    for (int im = 0; im < 2; im++) {
#pragma unroll
        for (int in = 0; in < 4; in++) {
            const int row = m0 + mb + im * 16 + g;
            const int col = n0 + nb + in * 8 + tig * 2;
            float bx = 0.f, by = 0.f;
            if (bias) { bx = bias[col]; by = bias[col + 1]; }
            float2 o0 = make_float2(acc[im][in][0] + bx, acc[im][in][1] + by);
            float2 o1 = make_float2(acc[im][in][2] + bx, acc[im][in][3] + by);
            if (addend) {
                const float2 r0 = *(const float2*)&addend[(long)row * N + col];
                const float2 r1 = *(const float2*)&addend[(long)(row + 8) * N + col];
                o0.x += r0.x; o0.y += r0.y;
                o1.x += r1.x; o1.y += r1.y;
            }
            *(float2*)&C[(long)row * N + col] = o0;
            *(float2*)&C[(long)(row + 8) * N + col] = o1;
        }
    }
}

// ---------------------------------------------------------------------------
// 256-thread core: 64x64 tile, 8 warps (2m x 4n), warp tile 32x16. (gemm_fin)
// Higher occupancy -> hides K=256 pipeline latency.
// ---------------------------------------------------------------------------
__device__ __forceinline__ void gemm_core_256(
    const float* __restrict__ A, int lda,
    const float* __restrict__ B, int ldb, int K,
    const float* __restrict__ addend,
    float* __restrict__ C, int N, int m0, int n0)
{
    __shared__ float As[STAGES][64 * LDA];
    __shared__ float Bs[STAGES][16 * LDB];

    const int tid = threadIdx.x;
    const int wid = tid >> 5;
    const int lane = tid & 31;
    const int g = lane >> 2;
    const int tig = lane & 3;
    const int warp_m = wid >> 2;   // 0..1
    const int warp_n = wid & 3;    // 0..3

    const int ar = tid >> 2;          // 0..63
    const int ak = (tid & 3) << 2;    // 0,4,8,12
    const int br = tid >> 4;          // 0..15
    const int bc = (tid & 15) << 2;   // 0..60

    uint32_t as_s = (uint32_t)__cvta_generic_to_shared(&As[0][0]);
    uint32_t bs_s = (uint32_t)__cvta_generic_to_shared(&Bs[0][0]);

    const int NT = K >> 4;

    float acc[2][2][4];
#pragma unroll
    for (int i = 0; i < 2; i++)
#pragma unroll
        for (int j = 0; j < 2; j++)
#pragma unroll
            for (int q = 0; q < 4; q++) acc[i][j][q] = 0.f;

    auto issue = [&](int stage, int kt) {
        const int kg = kt << 4;
        const float* s0 = A + (long)(m0 + ar) * lda + kg + ak;
        uint32_t d0 = as_s + stage * ABYTES + (ar * LDA + ak) * 4;
        CP16(d0, s0);
        const float* sb = B + (long)(kg + br) * ldb + n0 + bc;
        uint32_t db = bs_s + stage * BBYTES + (br * LDB + bc) * 4;
        CP16(db, sb);
    };

#pragma unroll
    for (int p = 0; p < STAGES - 1; p++) {
        if (p < NT) issue(p, p);
        CP_COMMIT();
    }

    for (int t = 0; t < NT; t++) {
        const int st = t & (STAGES - 1);
        CP_WAIT2();
        __syncthreads();

        if (t + STAGES - 1 < NT) issue((t + STAGES - 1) & (STAGES - 1), t + STAGES - 1);
        CP_COMMIT();

        const float* as = As[st];
        const float* bs = Bs[st];
        const int mb = warp_m * 32;
        const int nb = warp_n * 16;
#pragma unroll
        for (int ks = 0; ks < 2; ks++) {
            const int k0 = ks << 3;
            uint32_t a[2][4], b[2][2];
#pragma unroll
            for (int im = 0; im < 2; im++) {
                const float* ap = as + (mb + im * 16 + g) * LDA;
                a[im][0] = f2tf32(ap[k0 + tig]);
                a[im][1] = f2tf32(ap[8 * LDA + k0 + tig]);
                a[im][2] = f2tf32(ap[k0 + tig + 4]);
                a[im][3] = f2tf32(ap[8 * LDA + k0 + tig + 4]);
            }
#pragma unroll
            for (int in = 0; in < 2; in++) {
                const int nc = nb + in * 8 + g;
                b[in][0] = f2tf32(bs[(k0 + tig) * LDB + nc]);
                b[in][1] = f2tf32(bs[(k0 + tig + 4) * LDB + nc]);
            }
#pragma unroll
            for (int im = 0; im < 2; im++)
#pragma unroll
                for (int in = 0; in < 2; in++)
                    mma_tf32(acc[im][in], a[im], b[in]);
        }
        __syncthreads();
    }

    const int mb = warp_m * 32;
    const int nb = warp_n * 16;
#pragma unroll
    for (int im = 0; im < 2; im++) {
#pragma unroll
        for (int in = 0; in < 2; in++) {
            const int row = m0 + mb + im * 16 + g;
            const int col = n0 + nb + in * 8 + tig * 2;
            float2 o0 = make_float2(acc[im][in][0], acc[im][in][1]);
            float2 o1 = make_float2(acc[im][in][2], acc[im][in][3]);
            if (addend) {
                const float2 r0 = *(const float2*)&addend[(long)row * N + col];
                const float2 r1 = *(const float2*)&addend[(long)(row + 8) * N + col];
                o0.x += r0.x; o0.y += r0.y;
                o1.x += r1.x; o1.y += r1.y;
            }
            *(float2*)&C[(long)row * N + col] = o0;
            *(float2*)&C[(long)(row + 8) * N + col] = o1;
        }
    }
}

// Four independent 1024x512x512 jobs selected by blockIdx.z
struct Job {
    const float* A;
    const float* B;
    const float* bias;
    float* C;
};

__global__ __launch_bounds__(128) void gemm4(Job j0, Job j1, Job j2, Job j3)
{
    Job j = (blockIdx.z == 0) ? j0 : (blockIdx.z == 1) ? j1
          : (blockIdx.z == 2) ? j2 : j3;
    gemm_core(j.A, Ddim, j.B, Ddim, Ddim, j.bias, nullptr, j.C, Ddim,
              blockIdx.y * 64, blockIdx.x * 64);
}

// Final: out[b] = attn[b] @ pre1[b] + pre2[b]   (256 x 512, K=256 per batch)
__global__ __launch_bounds__(256) void gemm_fin(
    const float* __restrict__ attn, const float* __restrict__ pre1,
    const float* __restrict__ pre2, float* __restrict__ out)
{
    const int z = blockIdx.z;
    gemm_core_256(attn + (long)z * Tdim * Sdim, Sdim,
                  pre1 + (long)z * Sdim * Ddim, Ddim, Sdim,
                  pre2 + (long)z * Tdim * Ddim,
                  out + (long)z * Tdim * Ddim, Ddim,
                  blockIdx.y * 64, blockIdx.x * 64);
}

// ---------------------------------------------------------------------------
// score[b,t,s] = sum_d v[d] * tanh(wq[b,t,d] + uh[b,s,d])   (MUFU-bound)
// ---------------------------------------------------------------------------
__global__ __launch_bounds__(256) void score_kernel(
    const float* __restrict__ wq, const float* __restrict__ uh,
    const float* __restrict__ v, float* __restrict__ sc)
{
    __shared__ float Aq[32][33];
    __shared__ float Au[32][33];
    __shared__ float vs[32];

    const int b = blockIdx.z;
    const int t0 = blockIdx.y * 32;
    const int s0 = blockIdx.x * 32;
    const int tid = threadIdx.x;
    const int tx = tid & 15, ty = tid >> 4;

    const float* wqb = wq + ((long)b * Tdim + t0) * Ddim;
    const float* uhb = uh + ((long)b * Sdim + s0) * Ddim;

    const int lr = tid >> 3;
    const int lc = (tid & 7) << 2;

    float acc00 = 0.f, acc01 = 0.f, acc10 = 0.f, acc11 = 0.f;

    for (int d0 = 0; d0 < Ddim; d0 += 32) {
        float4 q = *(const float4*)&wqb[(long)lr * Ddim + d0 + lc];
        Aq[lc + 0][lr] = q.x;
        Aq[lc + 1][lr] = q.y;
        Aq[lc + 2][lr] = q.z;
        Aq[lc + 3][lr] = q.w;
        float4 u = *(const float4*)&uhb[(long)lr * Ddim + d0 + lc];
        Au[lc + 0][lr] = u.x;
        Au[lc + 1][lr] = u.y;
        Au[lc + 2][lr] = u.z;
        Au[lc + 3][lr] = u.w;
        if (tid < 32) vs[tid] = v[d0 + tid];
        __syncthreads();

#pragma unroll
        for (int dk = 0; dk < 32; dk++) {
            float vv = vs[dk];
            float a0 = Aq[dk][ty * 2 + 0];
            float a1 = Aq[dk][ty * 2 + 1];
            float u0 = Au[dk][tx * 2 + 0];
            float u1 = Au[dk][tx * 2 + 1];
            acc00 += vv * tanh_fast(a0 + u0);
            acc01 += vv * tanh_fast(a0 + u1);
            acc10 += vv * tanh_fast(a1 + u0);
            acc11 += vv * tanh_fast(a1 + u1);
        }
        __syncthreads();
    }

    float* scp = sc + ((long)b * Tdim + t0) * Sdim + s0;
    scp[(long)(ty * 2 + 0) * Sdim + tx * 2 + 0] = acc00;
    scp[(long)(ty * 2 + 0) * Sdim + tx * 2 + 1] = acc01;
    scp[(long)(ty * 2 + 1) * Sdim + tx * 2 + 0] = acc10;
    scp[(long)(ty * 2 + 1) * Sdim + tx * 2 + 1] = acc11;
}

// ---------------------------------------------------------------------------
// Masked softmax: warp-per-row, 8 rows/block. Reference semantics:
// max over ALL s, zero masked entries, renormalize.
// ---------------------------------------------------------------------------
__global__ __launch_bounds__(256) void softmax_kernel(
    float* __restrict__ sc, const int* __restrict__ mask,
    float* __restrict__ attn_out)
{
    const int warp = threadIdx.x >> 5;
    const int lane = threadIdx.x & 31;
    const int row = blockIdx.x * 8 + warp;   // b*T + t
    const int b = row >> 8;                  // row / Tdim

    float* rp = sc + (long)row * Sdim;
    const int* mp = mask + b * Sdim;

    float x[8];
    float m = -1e30f;
#pragma unroll
    for (int i = 0; i < 8; i++) {
        x[i] = rp[i * 32 + lane];
        m = fmaxf(m, x[i]);
    }
#pragma unroll
    for (int o = 16; o > 0; o >>= 1)
        m = fmaxf(m, __shfl_xor_sync(0xffffffffu, m, o));

    float e[8];
    float sum = 0.f;
#pragma unroll
    for (int i = 0; i < 8; i++) {
        float keep = 1.0f - (float)mp[i * 32 + lane];
        e[i] = __expf(x[i] - m) * keep;
        sum += e[i];
    }
#pragma unroll
    for (int o = 16; o > 0; o >>= 1)
        sum += __shfl_xor_sync(0xffffffffu, sum, o);

    const float inv = 1.0f / sum;
    float* ap = attn_out ? attn_out + (long)row * Sdim : nullptr;
#pragma unroll
    for (int i = 0; i < 8; i++) {
        float a = e[i] * inv;
        rp[i * 32 + lane] = a;
        if (ap) ap[i * 32 + lane] = a;
    }
}

// ---------------------------------------------------------------------------
extern "C" void kernel_launch(void* const* d_in, const int* in_sizes, int n_in,
                              void* d_out, int out_size)
{
    const float* out_in = (const float*)d_in[0];  // (B,T,D)
    const float* ctx    = (const float*)d_in[1];  // (B,S,D)
    const int*   mask   = (const int*)d_in[2];    // (B,S)
    const float* Wq     = (const float*)d_in[3];  // (D,D)
    const float* bq     = (const float*)d_in[4];  // (D,)
    const float* Wc     = (const float*)d_in[5];  // (D,D)
    const float* v      = (const float*)d_in[6];  // (D,)
    const float* Wout   = (const float*)d_in[7];  // (2D,D)
    const float* bout   = (const float*)d_in[8];  // (D,)

    float *p_wq, *p_uh, *p_sc, *p_pre1, *p_pre2;
    cudaGetSymbolAddress((void**)&p_wq, g_wq);
    cudaGetSymbolAddress((void**)&p_uh, g_uh);
    cudaGetSymbolAddress((void**)&p_sc, g_sc);
    cudaGetSymbolAddress((void**)&p_pre1, g_pre1);
    cudaGetSymbolAddress((void**)&p_pre2, g_pre2);

    const long BTD = (long)Bdim * Tdim * Ddim;  // 524288
    const long BTS = (long)Bdim * Tdim * Sdim;  // 262144
    float* out_f = (float*)d_out;
    float* attn_out = ((long)out_size >= BTD + BTS) ? (out_f + BTD) : nullptr;

    // 1) Four fused 1024x512x512 GEMMs:
    //    z0: wq   = output @ Wq + bq
    //    z1: uh   = context @ Wc
    //    z2: pre1 = context @ Wout[0:D]
    //    z3: pre2 = output @ Wout[D:2D] + bout
    Job j0{out_in, Wq, bq, p_wq};
    Job j1{ctx, Wc, nullptr, p_uh};
    Job j2{ctx, Wout, nullptr, p_pre1};
    Job j3{out_in, Wout + (long)Ddim * Ddim, bout, p_pre2};
    gemm4<<<dim3(Ddim / 64, (Bdim * Tdim) / 64, 4), 128>>>(j0, j1, j2, j3);

    // 2) score
    score_kernel<<<dim3(Sdim / 32, Tdim / 32, Bdim), 256>>>(p_wq, p_uh, v, p_sc);

    // 3) masked softmax (attn in-place in g_sc, also to d_out attn region)
    softmax_kernel<<<(Bdim * Tdim) / 8, 256>>>(p_sc, mask, attn_out);

    // 4) out = attn @ pre1 + pre2   (batched 256x512, K=256)
    gemm_fin<<<dim3(Ddim / 64, Tdim / 64, Bdim), 256>>>(p_sc, p_pre1, p_pre2, out_f);
}